// round 15
// baseline (speedup 1.0000x reference)
#include <cuda_runtime.h>
#include <cuda_bf16.h>
#include <cstdint>
#include <cstddef>

#define SEQ    256
#define BATCH  64
#define VOCAB  128
#define EMBED  256
#define HIDDEN 1024
#define HS     (HIDDEN * BATCH)
#define NCTA   128
#define NMMA   96
#define HP     264                  // padded k-pitch for h smem (bf16 elems)
#define OFF_W   0                   // W fragments: 256 frags x 512B = 131072
#define OFF_HHI 131072              // h hi plane: 64 x 264 x 2B = 33792
#define OFF_HLO 164864              // h lo plane: 33792
#define SMEM_USED 198656
#define SMEMB   (SMEM_USED + 1024)
#define PART_STRIDE (3072 * 64)

typedef unsigned long long u64;
typedef unsigned int u32;

// ---------------- device scratch (allocations forbidden) ----------------
__device__ float g_tab[3 * VOCAB * HIDDEN];
__device__ float g_hs [(size_t)(SEQ + 1) * HS];                  // fp32 h states [t][k][b]
__device__ __align__(16) __nv_bfloat16 g_hbf_hi[BATCH * HIDDEN]; // current h, [b][k]
__device__ __align__(16) __nv_bfloat16 g_hbf_lo[BATCH * HIDDEN];
__device__ float g_part[4 * PART_STRIDE];                        // partials [ks][grow][b]
__device__ u32 g_count;
__device__ u32 g_gen;

// ---------------- helpers ----------------
__device__ __forceinline__ u64 pack2(float x) {
    u64 r; asm("mov.b64 %0, {%1, %1};" : "=l"(r) : "f"(x)); return r;
}
__device__ __forceinline__ void ffma2(u64& d, u64 a, u64 b) {
    asm volatile("fma.rn.f32x2 %0, %1, %2, %0;" : "+l"(d) : "l"(a), "l"(b));
}
__device__ __forceinline__ void unpack2(u64 v, float& lo, float& hi) {
    asm("mov.b64 {%0, %1}, %2;" : "=f"(lo), "=f"(hi) : "l"(v));
}
__device__ __forceinline__ void cpasync16(u32 saddr, const void* gaddr) {
    asm volatile("cp.async.cg.shared.global [%0], [%1], 16;" :: "r"(saddr), "l"(gaddr));
}
__device__ __forceinline__ void cpcommit() { asm volatile("cp.async.commit_group;"); }
__device__ __forceinline__ float fsigmoid(float a) {
    return __fdividef(1.f, 1.f + __expf(-a));
}
__device__ __forceinline__ u32 ld_acquire(const u32* p) {
    u32 v; asm volatile("ld.acquire.gpu.u32 %0, [%1];" : "=r"(v) : "l"(p) : "memory"); return v;
}
__device__ __forceinline__ void st_release(u32* p, u32 v) {
    asm volatile("st.release.gpu.u32 [%0], %1;" :: "l"(p), "r"(v) : "memory");
}
__device__ __forceinline__ u32 smem_u32(const void* p) {
    return (u32)__cvta_generic_to_shared(p);
}
// m16n8k16 row.col bf16 -> f32
__device__ __forceinline__ void mma16816(float* d, uint4 a, u32 b0, u32 b1) {
    asm volatile(
        "mma.sync.aligned.m16n8k16.row.col.f32.bf16.bf16.f32 "
        "{%0,%1,%2,%3}, {%4,%5,%6,%7}, {%8,%9}, {%0,%1,%2,%3};"
        : "+f"(d[0]), "+f"(d[1]), "+f"(d[2]), "+f"(d[3])
        : "r"(a.x), "r"(a.y), "r"(a.z), "r"(a.w), "r"(b0), "r"(b1));
}
__device__ __forceinline__ u32 packbf2(float a, float b) {
    __nv_bfloat162 t = __floats2bfloat162_rn(a, b);
    return *(u32*)&t;
}

// ---------------- single-word global barrier, phases 1..511 ----------------
__device__ __forceinline__ void gbar(u32 p)
{
    __syncthreads();
    if (threadIdx.x == 0) {
        __threadfence();
        const u32 old = atomicAdd(&g_count, 1u);
        if (old == (u32)NCTA * p - 1u) st_release(&g_gen, p);
        while (ld_acquire(&g_gen) < p) { }
    }
    __syncthreads();
}

// ---------------- kernel 1: vocab tables ----------------
__global__ void k_tables(const float* __restrict__ emb,
                         const float* __restrict__ rxw, const float* __restrict__ zxw,
                         const float* __restrict__ nxw,
                         const float* __restrict__ rxb, const float* __restrict__ zxb,
                         const float* __restrict__ nxb)
{
    __shared__ float sEmb[32 * 256];
    const int tid = threadIdx.x, m = blockIdx.y;
    const int j = blockIdx.x * 32 + (tid >> 3), lane = tid & 7;
    const float* W = (m == 0) ? rxw : (m == 1) ? zxw : nxw;
    const float* B = (m == 0) ? rxb : (m == 1) ? zxb : nxb;
    float wreg[32];
#pragma unroll
    for (int i = 0; i < 32; i++) wreg[i] = W[j * EMBED + lane + 8 * i];
    const float bias = B[j];
    for (int p = 0; p < 4; p++) {
        __syncthreads();
        for (int idx = tid; idx < 32 * 256; idx += 256)
            sEmb[idx] = emb[(p * 32 + (idx >> 8)) * EMBED + (idx & 255)];
        __syncthreads();
        for (int v = 0; v < 32; v++) {
            const float* e = &sEmb[v * 256 + lane];
            float s = 0.f;
#pragma unroll
            for (int i = 0; i < 32; i++) s += wreg[i] * e[8 * i];
            s += __shfl_xor_sync(0xffffffffu, s, 1);
            s += __shfl_xor_sync(0xffffffffu, s, 2);
            s += __shfl_xor_sync(0xffffffffu, s, 4);
            if (lane == 0) g_tab[(m * VOCAB + p * 32 + v) * HIDDEN + j] = s + bias;
        }
    }
}

// ---------------- kernel 2: hprev prep ----------------
__global__ void k_tr(const float* __restrict__ hprev)
{
    const int o0 = (blockIdx.x * 256 + threadIdx.x) * 4;
#pragma unroll
    for (int i = 0; i < 4; i++) {
        const int o = o0 + i;
        const int k = o >> 6, b = o & 63;
        const float v = hprev[b * HIDDEN + k];
        g_hs[k * 64 + b] = v;
        const __nv_bfloat16 hi = __float2bfloat16_rn(v);
        g_hbf_hi[b * HIDDEN + k] = hi;
        g_hbf_lo[b * HIDDEN + k] = __float2bfloat16_rn(v - __bfloat162float(hi));
    }
}

// ---------------- kernel 3: persistent GRU recurrence (mma.sync bf16 hi/lo) ----------------
// CTAs 0..95: MMA role. cta = mg*4 + ks; mg: 128 W-rows (gate mg>>3, j (mg&7)*128..+128),
//             ks: k-slice ks*256..+256. Warp owns 1 M-tile (16 rows) x 8 N-tiles x 16 K-tiles.
// CTAs 96..127: updater role: 32 j x 64 b each.
__global__ void __launch_bounds__(256, 1)
k_recur(const int* __restrict__ x,
        const float* __restrict__ rhw, const float* __restrict__ rhb,
        const float* __restrict__ zhw, const float* __restrict__ zhb,
        const float* __restrict__ nhw, const float* __restrict__ nhb)
{
    extern __shared__ char smraw[];
    const u32 sbr = smem_u32(smraw);
    char* smc = smraw + (((sbr + 1023u) & ~1023u) - sbr);
    const u32 sb = smem_u32(smc);

    const int tid = threadIdx.x;
    const int cta = blockIdx.x;

    if (cta < NMMA) {
        // ================= MMA role =================
        const int mg = cta >> 2, ks = cta & 3;
        const int gate  = mg >> 3;
        const int jbase = (mg & 7) * 128;
        const float* Wg = (gate == 0) ? rhw : (gate == 1) ? zhw : nhw;

        const int w = tid >> 5, lane = tid & 31;
        const int gid = lane >> 2, c4 = lane & 3;

        // ---- one-time: build W fragments (hi/lo) in per-lane order ----
        {
            const int ja = jbase + w * 16 + gid;      // rows ja, ja+8
            const int k0 = ks * 256 + 2 * c4;
            for (int kt = 0; kt < 16; kt++) {
                const int kk = k0 + kt * 16;
                const float2 p00 = *(const float2*)(Wg + (size_t)ja * HIDDEN + kk);
                const float2 p10 = *(const float2*)(Wg + (size_t)(ja + 8) * HIDDEN + kk);
                const float2 p02 = *(const float2*)(Wg + (size_t)ja * HIDDEN + kk + 8);
                const float2 p12 = *(const float2*)(Wg + (size_t)(ja + 8) * HIDDEN + kk + 8);
                const float e[8] = {p00.x, p00.y, p10.x, p10.y, p02.x, p02.y, p12.x, p12.y};
                u32 hi[4], lo[4];
#pragma unroll
                for (int q = 0; q < 4; q++) {
                    const __nv_bfloat16 ha = __float2bfloat16_rn(e[2*q]);
                    const __nv_bfloat16 hb = __float2bfloat16_rn(e[2*q+1]);
                    const float la = e[2*q]   - __bfloat162float(ha);
                    const float lb = e[2*q+1] - __bfloat162float(hb);
                    hi[q] = ((u32)*(const unsigned short*)&ha) | (((u32)*(const unsigned short*)&hb) << 16);
                    lo[q] = packbf2(la, lb);
                }
                char* fb = smc + OFF_W + (size_t)((w * 16 + kt) * 2) * 512 + lane * 16;
                *(uint4*)fb         = make_uint4(hi[0], hi[1], hi[2], hi[3]);
                *(uint4*)(fb + 512) = make_uint4(lo[0], lo[1], lo[2], lo[3]);
            }
        }
        __syncthreads();

        const int grow = gate * 1024 + jbase + w * 16 + gid;
        float* pbase = g_part + (size_t)ks * PART_STRIDE + (size_t)grow * 64 + 2 * c4;

        for (int t = 0; t < SEQ; ++t) {
            if (t > 0) gbar(2u * t);                  // wait h(t) ready

            // load h slice hi/lo into padded smem
#pragma unroll
            for (int i = 0; i < 8; i++) {
                const int ci = tid + i * 256;         // 0..2047
                const int b = ci >> 5, ko = (ci & 31) * 8;
                const u32 d = sb + OFF_HHI + b * (HP * 2) + ko * 2;
                const size_t gofs = (size_t)b * HIDDEN + ks * 256 + ko;
                cpasync16(d, g_hbf_hi + gofs);
                cpasync16(d + (OFF_HLO - OFF_HHI), g_hbf_lo + gofs);
            }
            cpcommit();
            asm volatile("cp.async.wait_group 0;");
            __syncthreads();

            float acc[8][4];
#pragma unroll
            for (int nt = 0; nt < 8; nt++)
#pragma unroll
                for (int q = 0; q < 4; q++) acc[nt][q] = 0.f;

            for (int kt = 0; kt < 16; kt++) {
                const char* fb = smc + OFF_W + (size_t)((w * 16 + kt) * 2) * 512 + lane * 16;
                const uint4 ahi = *(const uint4*)fb;
                const uint4 alo = *(const uint4*)(fb + 512);
                const int kloc = kt * 16 + 2 * c4;
#pragma unroll
                for (int nt = 0; nt < 8; nt++) {
                    const char* hp = smc + OFF_HHI + ((nt * 8 + gid) * HP + kloc) * 2;
                    const u32 bh0 = *(const u32*)hp;
                    const u32 bh1 = *(const u32*)(hp + 16);
                    const u32 bl0 = *(const u32*)(hp + (OFF_HLO - OFF_HHI));
                    const u32 bl1 = *(const u32*)(hp + (OFF_HLO - OFF_HHI) + 16);
                    mma16816(acc[nt], ahi, bh0, bh1);
                    mma16816(acc[nt], ahi, bl0, bl1);
                    mma16816(acc[nt], alo, bh0, bh1);
                }
            }

            // store partials: rows grow, grow+8; cols nt*8 + 2c4 (+1)
#pragma unroll
            for (int nt = 0; nt < 8; nt++) {
                *(float2*)(pbase + nt * 8)       = make_float2(acc[nt][0], acc[nt][1]);
                *(float2*)(pbase + 512 + nt * 8) = make_float2(acc[nt][2], acc[nt][3]);
            }
            gbar(2u * t + 1u);                        // partials ready
        }
    } else {
        // ================= updater role =================
        float* sTab  = (float*)smc;                   // 12288 floats
        float* sBias = (float*)(smc + 49152);         // 96
        int*   sTok  = (int*)  (smc + 49536);         // 64
        const int u = cta - NMMA, jb = u * 32;

        for (int idx = tid; idx < 12288; idx += 256) {
            const int jl = idx & 31, gv = idx >> 5;
            sTab[idx] = g_tab[gv * HIDDEN + jb + jl];
        }
        if (tid < 96) {
            const int g = tid >> 5, jl = tid & 31;
            const float* B = (g == 0) ? rhb : (g == 1) ? zhb : nhb;
            sBias[tid] = B[jb + jl];
        }
        __syncthreads();

        const int jl = tid >> 3, bq = tid & 7;
        const int j  = jb + jl;

        for (int t = 0; t < SEQ; ++t) {
            if (tid < 64) sTok[tid] = x[t * BATCH + tid];
            gbar(2u * t + 1u);                        // wait partials

            float pre[3][8];
#pragma unroll
            for (int g = 0; g < 3; g++) {
                const float* pb = g_part + (size_t)(g * 1024 + j) * 64 + bq * 8;
                float4 a0 = *(const float4*)pb;
                float4 a1 = *(const float4*)(pb + 4);
#pragma unroll
                for (int ksp = 1; ksp < 4; ksp++) {
                    const float4 c0 = *(const float4*)(pb + (size_t)ksp * PART_STRIDE);
                    const float4 c1 = *(const float4*)(pb + (size_t)ksp * PART_STRIDE + 4);
                    a0.x += c0.x; a0.y += c0.y; a0.z += c0.z; a0.w += c0.w;
                    a1.x += c1.x; a1.y += c1.y; a1.z += c1.z; a1.w += c1.w;
                }
                pre[g][0] = a0.x; pre[g][1] = a0.y; pre[g][2] = a0.z; pre[g][3] = a0.w;
                pre[g][4] = a1.x; pre[g][5] = a1.y; pre[g][6] = a1.z; pre[g][7] = a1.w;
            }

            const float* hpp = g_hs + (size_t)t * HS + j * 64 + bq * 8;
            const float4 h0 = *(const float4*)hpp;
            const float4 h1 = *(const float4*)(hpp + 4);
            const float hprev8[8] = {h0.x, h0.y, h0.z, h0.w, h1.x, h1.y, h1.z, h1.w};

            float hn[8];
#pragma unroll
            for (int p = 0; p < 8; p++) {
                const int b = bq * 8 + p;
                const int v = sTok[b];
                const float ar = sTab[v * 32 + jl]          + pre[0][p] + sBias[jl];
                const float az = sTab[(128 + v) * 32 + jl]  + pre[1][p] + sBias[32 + jl];
                const float xn = sTab[(256 + v) * 32 + jl];
                const float r = fsigmoid(ar);
                const float z = fsigmoid(az);
                const float n = tanhf(xn + r * (pre[2][p] + sBias[64 + jl]));
                hn[p] = (1.f - z) * hprev8[p] + z * n;
            }

            float* ho = g_hs + (size_t)(t + 1) * HS + j * 64 + bq * 8;
            *(float4*)ho       = make_float4(hn[0], hn[1], hn[2], hn[3]);
            *(float4*)(ho + 4) = make_float4(hn[4], hn[5], hn[6], hn[7]);
#pragma unroll
            for (int p = 0; p < 8; p++) {
                const int b = bq * 8 + p;
                const __nv_bfloat16 hi = __float2bfloat16_rn(hn[p]);
                g_hbf_hi[b * HIDDEN + j] = hi;
                g_hbf_lo[b * HIDDEN + j] = __float2bfloat16_rn(hn[p] - __bfloat162float(hi));
            }

            if (t < SEQ - 1) gbar(2u * t + 2u);       // h(t+1) ready
        }
    }

    // ---- final arrive; last CTA resets barrier state for graph replays ----
    __syncthreads();
    if (tid == 0) {
        __threadfence();
        const u32 old = atomicAdd(&g_count, 1u);
        if (old == (u32)NCTA * 512u - 1u) {
            g_count = 0u;
            st_release(&g_gen, 0u);
        }
    }
}

// ---------------- kernel 4: logits ----------------
__global__ void __launch_bounds__(256, 2)
k_logits(const float* __restrict__ dw, const float* __restrict__ db,
         float* __restrict__ out)
{
    __shared__ float smem[8192];
    const int tid = threadIdx.x;
    const int t   = blockIdx.x;
    const int vg  = tid >> 3;
    const int bg  = tid & 7;

    const float* hsrc = g_hs + (size_t)(t + 1) * HS;
    const u32 smem_u = smem_u32(smem);

    const float* W0 = dw + (vg * 4 + 0) * HIDDEN;
    const float* W1 = dw + (vg * 4 + 1) * HIDDEN;
    const float* W2 = dw + (vg * 4 + 2) * HIDDEN;
    const float* W3 = dw + (vg * 4 + 3) * HIDDEN;

    u64 acc[4][4];
#pragma unroll
    for (int vi = 0; vi < 4; vi++)
#pragma unroll
        for (int p = 0; p < 4; p++) acc[vi][p] = 0ull;

    {
#pragma unroll
        for (int i = 0; i < 4; i++) {
            const int slot = tid + i * 256;
            cpasync16(smem_u + slot * 16, hsrc + slot * 4);
        }
        cpcommit();
    }

    for (int kt = 0; kt < 16; ++kt) {
        const int buf = kt & 1;
        if (kt < 15) {
            const float* src = hsrc + (kt + 1) * 64 * 64;
            const u32 dst = smem_u + (buf ^ 1) * 4096 * 4;
#pragma unroll
            for (int i = 0; i < 4; i++) {
                const int slot = tid + i * 256;
                cpasync16(dst + slot * 16, src + slot * 4);
            }
            cpcommit();
            asm volatile("cp.async.wait_group 1;");
        } else {
            asm volatile("cp.async.wait_group 0;");
        }
        __syncthreads();

        const float* hb = smem + buf * 4096;
        const int kg0 = kt * 64;
#pragma unroll 4
        for (int c = 0; c < 16; c++) {
            const int kg = kg0 + c * 4;
            const float4 w0 = *(const float4*)(W0 + kg);
            const float4 w1 = *(const float4*)(W1 + kg);
            const float4 w2 = *(const float4*)(W2 + kg);
            const float4 w3 = *(const float4*)(W3 + kg);
#pragma unroll
            for (int i = 0; i < 4; i++) {
                const int kk = c * 4 + i;
                const u64* hp = (const u64*)(hb + kk * 64 + bg * 8);
                const u64 h0 = hp[0], h1 = hp[1], h2 = hp[2], h3 = hp[3];
                const u64 p0 = pack2((&w0.x)[i]);
                const u64 p1 = pack2((&w1.x)[i]);
                const u64 p2 = pack2((&w2.x)[i]);
                const u64 p3 = pack2((&w3.x)[i]);
                ffma2(acc[0][0], p0, h0); ffma2(acc[0][1], p0, h1);
                ffma2(acc[0][2], p0, h2); ffma2(acc[0][3], p0, h3);
                ffma2(acc[1][0], p1, h0); ffma2(acc[1][1], p1, h1);
                ffma2(acc[1][2], p1, h2); ffma2(acc[1][3], p1, h3);
                ffma2(acc[2][0], p2, h0); ffma2(acc[2][1], p2, h1);
                ffma2(acc[2][2], p2, h2); ffma2(acc[2][3], p2, h3);
                ffma2(acc[3][0], p3, h0); ffma2(acc[3][1], p3, h1);
                ffma2(acc[3][2], p3, h2); ffma2(acc[3][3], p3, h3);
            }
        }
        __syncthreads();
    }

    const float4 dbv = *(const float4*)(db + vg * 4);
#pragma unroll
    for (int p = 0; p < 4; p++) {
        float l0, h0, l1, h1, l2, h2, l3, h3;
        unpack2(acc[0][p], l0, h0); unpack2(acc[1][p], l1, h1);
        unpack2(acc[2][p], l2, h2); unpack2(acc[3][p], l3, h3);
        const int b0 = bg * 8 + 2 * p;
        float4 r0 = make_float4(l0 + dbv.x, l1 + dbv.y, l2 + dbv.z, l3 + dbv.w);
        float4 r1 = make_float4(h0 + dbv.x, h1 + dbv.y, h2 + dbv.z, h3 + dbv.w);
        *(float4*)(out + (size_t)(t * 64 + b0    ) * VOCAB + vg * 4) = r0;
        *(float4*)(out + (size_t)(t * 64 + b0 + 1) * VOCAB + vg * 4) = r1;
    }
}

// ---------------- kernel 5: h_final ----------------
__global__ void k_final(float* __restrict__ out2)
{
    const int o0 = (blockIdx.x * 256 + threadIdx.x) * 4;
    const float* src = g_hs + (size_t)SEQ * HS;
#pragma unroll
    for (int i = 0; i < 4; i++) {
        const int o = o0 + i;
        const int b = o >> 10, k = o & 1023;
        out2[b * HIDDEN + k] = src[k * 64 + b];
    }
}

// ---------------- launcher ----------------
extern "C" void kernel_launch(void* const* d_in, const int* in_sizes, int n_in,
                              void* d_out, int out_size)
{
    const int*   x    = (const int*)  d_in[0];
    const float* hprev= (const float*)d_in[1];
    const float* emb  = (const float*)d_in[2];
    const float* rxw  = (const float*)d_in[3];
    const float* rxb  = (const float*)d_in[4];
    const float* rhw  = (const float*)d_in[5];
    const float* rhb  = (const float*)d_in[6];
    const float* zxw  = (const float*)d_in[7];
    const float* zxb  = (const float*)d_in[8];
    const float* zhw  = (const float*)d_in[9];
    const float* zhb  = (const float*)d_in[10];
    const float* nxw  = (const float*)d_in[11];
    const float* nxb  = (const float*)d_in[12];
    const float* nhw  = (const float*)d_in[13];
    const float* nhb  = (const float*)d_in[14];
    const float* dw   = (const float*)d_in[15];
    const float* db   = (const float*)d_in[16];
    float* out = (float*)d_out;

    static bool attr_set = false;
    if (!attr_set) {
        cudaFuncSetAttribute(k_recur, cudaFuncAttributeMaxDynamicSharedMemorySize, SMEMB);
        attr_set = true;
    }

    k_tables<<<dim3(32, 3), 256>>>(emb, rxw, zxw, nxw, rxb, zxb, nxb);
    k_tr<<<64, 256>>>(hprev);
    k_recur<<<NCTA, 256, SMEMB>>>(x, rhw, rhb, zhw, zhb, nhw, nhb);
    k_logits<<<256, 256>>>(dw, db, out);
    k_final<<<64, 256>>>(out + (size_t)SEQ * BATCH * VOCAB);
}

// round 16
// speedup vs baseline: 1.0074x; 1.0074x over previous
#include <cuda_runtime.h>
#include <cuda_bf16.h>
#include <cstdint>
#include <cstddef>

#define SEQ    256
#define BATCH  64
#define VOCAB  128
#define EMBED  256
#define HIDDEN 1024
#define HS     (HIDDEN * BATCH)
#define NCTA   128
#define NMMA   96
#define HP     264                  // padded k-pitch for h smem (bf16 elems)
#define OFF_W   0                   // W fragments: 256 frags x 512B = 131072
#define OFF_HHI 131072              // h hi plane: 64 x 264 x 2B = 33792
#define OFF_HLO 164864              // h lo plane: 33792
#define SMEM_USED 198656
#define SMEMB   (SMEM_USED + 1024)
#define PART_STRIDE (3072 * 64)

typedef unsigned long long u64;
typedef unsigned int u32;

// ---------------- device scratch (allocations forbidden) ----------------
__device__ float g_tab[3 * VOCAB * HIDDEN];
__device__ float g_hs [(size_t)(SEQ + 1) * HS];                  // fp32 h states [t][k][b]
__device__ __align__(16) __nv_bfloat16 g_hbf_hi[BATCH * HIDDEN]; // current h, [b][k]
__device__ __align__(16) __nv_bfloat16 g_hbf_lo[BATCH * HIDDEN];
__device__ float g_part[4 * PART_STRIDE];                        // partials [ks][grow][b]
__device__ u32 g_count;
__device__ u32 g_gen;

// ---------------- helpers ----------------
__device__ __forceinline__ u64 pack2(float x) {
    u64 r; asm("mov.b64 %0, {%1, %1};" : "=l"(r) : "f"(x)); return r;
}
__device__ __forceinline__ void ffma2(u64& d, u64 a, u64 b) {
    asm volatile("fma.rn.f32x2 %0, %1, %2, %0;" : "+l"(d) : "l"(a), "l"(b));
}
__device__ __forceinline__ void unpack2(u64 v, float& lo, float& hi) {
    asm("mov.b64 {%0, %1}, %2;" : "=f"(lo), "=f"(hi) : "l"(v));
}
__device__ __forceinline__ void cpasync16(u32 saddr, const void* gaddr) {
    asm volatile("cp.async.cg.shared.global [%0], [%1], 16;" :: "r"(saddr), "l"(gaddr));
}
__device__ __forceinline__ void cpcommit() { asm volatile("cp.async.commit_group;"); }
__device__ __forceinline__ float fsigmoid(float a) {
    return __fdividef(1.f, 1.f + __expf(-a));
}
__device__ __forceinline__ u32 ld_acquire(const u32* p) {
    u32 v; asm volatile("ld.acquire.gpu.u32 %0, [%1];" : "=r"(v) : "l"(p) : "memory"); return v;
}
__device__ __forceinline__ void st_release(u32* p, u32 v) {
    asm volatile("st.release.gpu.u32 [%0], %1;" :: "l"(p), "r"(v) : "memory");
}
__device__ __forceinline__ u32 smem_u32(const void* p) {
    return (u32)__cvta_generic_to_shared(p);
}
// m16n8k16 row.col bf16 -> f32
__device__ __forceinline__ void mma16816(float* d, uint4 a, u32 b0, u32 b1) {
    asm volatile(
        "mma.sync.aligned.m16n8k16.row.col.f32.bf16.bf16.f32 "
        "{%0,%1,%2,%3}, {%4,%5,%6,%7}, {%8,%9}, {%0,%1,%2,%3};"
        : "+f"(d[0]), "+f"(d[1]), "+f"(d[2]), "+f"(d[3])
        : "r"(a.x), "r"(a.y), "r"(a.z), "r"(a.w), "r"(b0), "r"(b1));
}
__device__ __forceinline__ u32 packbf2(float a, float b) {
    __nv_bfloat162 t = __floats2bfloat162_rn(a, b);
    return *(u32*)&t;
}

// ---------------- single-word global barrier, phases 1..511 ----------------
__device__ __forceinline__ void gbar(u32 p)
{
    __syncthreads();
    if (threadIdx.x == 0) {
        __threadfence();
        const u32 old = atomicAdd(&g_count, 1u);
        if (old == (u32)NCTA * p - 1u) st_release(&g_gen, p);
        while (ld_acquire(&g_gen) < p) { }
    }
    __syncthreads();
}

// ---------------- kernel 1: vocab tables ----------------
__global__ void k_tables(const float* __restrict__ emb,
                         const float* __restrict__ rxw, const float* __restrict__ zxw,
                         const float* __restrict__ nxw,
                         const float* __restrict__ rxb, const float* __restrict__ zxb,
                         const float* __restrict__ nxb)
{
    __shared__ float sEmb[32 * 256];
    const int tid = threadIdx.x, m = blockIdx.y;
    const int j = blockIdx.x * 32 + (tid >> 3), lane = tid & 7;
    const float* W = (m == 0) ? rxw : (m == 1) ? zxw : nxw;
    const float* B = (m == 0) ? rxb : (m == 1) ? zxb : nxb;
    float wreg[32];
#pragma unroll
    for (int i = 0; i < 32; i++) wreg[i] = W[j * EMBED + lane + 8 * i];
    const float bias = B[j];
    for (int p = 0; p < 4; p++) {
        __syncthreads();
        for (int idx = tid; idx < 32 * 256; idx += 256)
            sEmb[idx] = emb[(p * 32 + (idx >> 8)) * EMBED + (idx & 255)];
        __syncthreads();
        for (int v = 0; v < 32; v++) {
            const float* e = &sEmb[v * 256 + lane];
            float s = 0.f;
#pragma unroll
            for (int i = 0; i < 32; i++) s += wreg[i] * e[8 * i];
            s += __shfl_xor_sync(0xffffffffu, s, 1);
            s += __shfl_xor_sync(0xffffffffu, s, 2);
            s += __shfl_xor_sync(0xffffffffu, s, 4);
            if (lane == 0) g_tab[(m * VOCAB + p * 32 + v) * HIDDEN + j] = s + bias;
        }
    }
}

// ---------------- kernel 2: hprev prep ----------------
__global__ void k_tr(const float* __restrict__ hprev)
{
    const int o0 = (blockIdx.x * 256 + threadIdx.x) * 4;
#pragma unroll
    for (int i = 0; i < 4; i++) {
        const int o = o0 + i;
        const int k = o >> 6, b = o & 63;
        const float v = hprev[b * HIDDEN + k];
        g_hs[k * 64 + b] = v;
        const __nv_bfloat16 hi = __float2bfloat16_rn(v);
        g_hbf_hi[b * HIDDEN + k] = hi;
        g_hbf_lo[b * HIDDEN + k] = __float2bfloat16_rn(v - __bfloat162float(hi));
    }
}

// ---------------- kernel 3: persistent GRU recurrence (mma.sync bf16 hi/lo) ----------------
// CTAs 0..95: MMA role. cta = mg*4 + ks; mg: 128 W-rows (gate mg>>3, j (mg&7)*128..+128),
//             ks: k-slice ks*256..+256. Warp owns 1 M-tile (16 rows) x 8 N-tiles x 16 K-tiles.
// CTAs 96..127: updater role: 32 j x 64 b each.
__global__ void __launch_bounds__(256, 1)
k_recur(const int* __restrict__ x,
        const float* __restrict__ rhw, const float* __restrict__ rhb,
        const float* __restrict__ zhw, const float* __restrict__ zhb,
        const float* __restrict__ nhw, const float* __restrict__ nhb)
{
    extern __shared__ char smraw[];
    const u32 sbr = smem_u32(smraw);
    char* smc = smraw + (((sbr + 1023u) & ~1023u) - sbr);
    const u32 sb = smem_u32(smc);

    const int tid = threadIdx.x;
    const int cta = blockIdx.x;

    if (cta < NMMA) {
        // ================= MMA role =================
        const int mg = cta >> 2, ks = cta & 3;
        const int gate  = mg >> 3;
        const int jbase = (mg & 7) * 128;
        const float* Wg = (gate == 0) ? rhw : (gate == 1) ? zhw : nhw;

        const int w = tid >> 5, lane = tid & 31;
        const int gid = lane >> 2, c4 = lane & 3;

        // ---- one-time: build W fragments (hi/lo) in per-lane order ----
        {
            const int ja = jbase + w * 16 + gid;      // rows ja, ja+8
            const int k0 = ks * 256 + 2 * c4;
            for (int kt = 0; kt < 16; kt++) {
                const int kk = k0 + kt * 16;
                const float2 p00 = *(const float2*)(Wg + (size_t)ja * HIDDEN + kk);
                const float2 p10 = *(const float2*)(Wg + (size_t)(ja + 8) * HIDDEN + kk);
                const float2 p02 = *(const float2*)(Wg + (size_t)ja * HIDDEN + kk + 8);
                const float2 p12 = *(const float2*)(Wg + (size_t)(ja + 8) * HIDDEN + kk + 8);
                const float e[8] = {p00.x, p00.y, p10.x, p10.y, p02.x, p02.y, p12.x, p12.y};
                u32 hi[4], lo[4];
#pragma unroll
                for (int q = 0; q < 4; q++) {
                    const __nv_bfloat16 ha = __float2bfloat16_rn(e[2*q]);
                    const __nv_bfloat16 hb = __float2bfloat16_rn(e[2*q+1]);
                    const float la = e[2*q]   - __bfloat162float(ha);
                    const float lb = e[2*q+1] - __bfloat162float(hb);
                    hi[q] = ((u32)*(const unsigned short*)&ha) | (((u32)*(const unsigned short*)&hb) << 16);
                    lo[q] = packbf2(la, lb);
                }
                char* fb = smc + OFF_W + (size_t)((w * 16 + kt) * 2) * 512 + lane * 16;
                *(uint4*)fb         = make_uint4(hi[0], hi[1], hi[2], hi[3]);
                *(uint4*)(fb + 512) = make_uint4(lo[0], lo[1], lo[2], lo[3]);
            }
        }
        __syncthreads();

        const int grow = gate * 1024 + jbase + w * 16 + gid;
        float* pbase = g_part + (size_t)ks * PART_STRIDE + (size_t)grow * 64 + 2 * c4;

        for (int t = 0; t < SEQ; ++t) {
            if (t > 0) gbar(2u * t);                  // wait h(t) ready

            // load h slice hi/lo into padded smem
#pragma unroll
            for (int i = 0; i < 8; i++) {
                const int ci = tid + i * 256;         // 0..2047
                const int b = ci >> 5, ko = (ci & 31) * 8;
                const u32 d = sb + OFF_HHI + b * (HP * 2) + ko * 2;
                const size_t gofs = (size_t)b * HIDDEN + ks * 256 + ko;
                cpasync16(d, g_hbf_hi + gofs);
                cpasync16(d + (OFF_HLO - OFF_HHI), g_hbf_lo + gofs);
            }
            cpcommit();
            asm volatile("cp.async.wait_group 0;");
            __syncthreads();

            float acc[8][4];
#pragma unroll
            for (int nt = 0; nt < 8; nt++)
#pragma unroll
                for (int q = 0; q < 4; q++) acc[nt][q] = 0.f;

            for (int kt = 0; kt < 16; kt++) {
                const char* fb = smc + OFF_W + (size_t)((w * 16 + kt) * 2) * 512 + lane * 16;
                const uint4 ahi = *(const uint4*)fb;
                const uint4 alo = *(const uint4*)(fb + 512);
                const int kloc = kt * 16 + 2 * c4;
#pragma unroll
                for (int nt = 0; nt < 8; nt++) {
                    const char* hp = smc + OFF_HHI + ((nt * 8 + gid) * HP + kloc) * 2;
                    const u32 bh0 = *(const u32*)hp;
                    const u32 bh1 = *(const u32*)(hp + 16);
                    const u32 bl0 = *(const u32*)(hp + (OFF_HLO - OFF_HHI));
                    const u32 bl1 = *(const u32*)(hp + (OFF_HLO - OFF_HHI) + 16);
                    mma16816(acc[nt], ahi, bh0, bh1);
                    mma16816(acc[nt], ahi, bl0, bl1);
                    mma16816(acc[nt], alo, bh0, bh1);
                }
            }

            // store partials: rows grow, grow+8; cols nt*8 + 2c4 (+1)
#pragma unroll
            for (int nt = 0; nt < 8; nt++) {
                *(float2*)(pbase + nt * 8)       = make_float2(acc[nt][0], acc[nt][1]);
                *(float2*)(pbase + 512 + nt * 8) = make_float2(acc[nt][2], acc[nt][3]);
            }
            gbar(2u * t + 1u);                        // partials ready
        }
    } else {
        // ================= updater role =================
        float* sTab  = (float*)smc;                   // 12288 floats
        float* sBias = (float*)(smc + 49152);         // 96
        int*   sTok  = (int*)  (smc + 49536);         // 64
        const int u = cta - NMMA, jb = u * 32;

        for (int idx = tid; idx < 12288; idx += 256) {
            const int jl = idx & 31, gv = idx >> 5;
            sTab[idx] = g_tab[gv * HIDDEN + jb + jl];
        }
        if (tid < 96) {
            const int g = tid >> 5, jl = tid & 31;
            const float* B = (g == 0) ? rhb : (g == 1) ? zhb : nhb;
            sBias[tid] = B[jb + jl];
        }
        __syncthreads();

        const int jl = tid >> 3, bq = tid & 7;
        const int j  = jb + jl;

        for (int t = 0; t < SEQ; ++t) {
            if (tid < 64) sTok[tid] = x[t * BATCH + tid];
            gbar(2u * t + 1u);                        // wait partials

            float pre[3][8];
#pragma unroll
            for (int g = 0; g < 3; g++) {
                const float* pb = g_part + (size_t)(g * 1024 + j) * 64 + bq * 8;
                float4 a0 = *(const float4*)pb;
                float4 a1 = *(const float4*)(pb + 4);
#pragma unroll
                for (int ksp = 1; ksp < 4; ksp++) {
                    const float4 c0 = *(const float4*)(pb + (size_t)ksp * PART_STRIDE);
                    const float4 c1 = *(const float4*)(pb + (size_t)ksp * PART_STRIDE + 4);
                    a0.x += c0.x; a0.y += c0.y; a0.z += c0.z; a0.w += c0.w;
                    a1.x += c1.x; a1.y += c1.y; a1.z += c1.z; a1.w += c1.w;
                }
                pre[g][0] = a0.x; pre[g][1] = a0.y; pre[g][2] = a0.z; pre[g][3] = a0.w;
                pre[g][4] = a1.x; pre[g][5] = a1.y; pre[g][6] = a1.z; pre[g][7] = a1.w;
            }

            const float* hpp = g_hs + (size_t)t * HS + j * 64 + bq * 8;
            const float4 h0 = *(const float4*)hpp;
            const float4 h1 = *(const float4*)(hpp + 4);
            const float hprev8[8] = {h0.x, h0.y, h0.z, h0.w, h1.x, h1.y, h1.z, h1.w};

            float hn[8];
#pragma unroll
            for (int p = 0; p < 8; p++) {
                const int b = bq * 8 + p;
                const int v = sTok[b];
                const float ar = sTab[v * 32 + jl]          + pre[0][p] + sBias[jl];
                const float az = sTab[(128 + v) * 32 + jl]  + pre[1][p] + sBias[32 + jl];
                const float xn = sTab[(256 + v) * 32 + jl];
                const float r = fsigmoid(ar);
                const float z = fsigmoid(az);
                const float n = tanhf(xn + r * (pre[2][p] + sBias[64 + jl]));
                hn[p] = (1.f - z) * hprev8[p] + z * n;
            }

            float* ho = g_hs + (size_t)(t + 1) * HS + j * 64 + bq * 8;
            *(float4*)ho       = make_float4(hn[0], hn[1], hn[2], hn[3]);
            *(float4*)(ho + 4) = make_float4(hn[4], hn[5], hn[6], hn[7]);
#pragma unroll
            for (int p = 0; p < 8; p++) {
                const int b = bq * 8 + p;
                const __nv_bfloat16 hi = __float2bfloat16_rn(hn[p]);
                g_hbf_hi[b * HIDDEN + j] = hi;
                g_hbf_lo[b * HIDDEN + j] = __float2bfloat16_rn(hn[p] - __bfloat162float(hi));
            }

            if (t < SEQ - 1) gbar(2u * t + 2u);       // h(t+1) ready
        }
    }

    // ---- final arrive; last CTA resets barrier state for graph replays ----
    __syncthreads();
    if (tid == 0) {
        __threadfence();
        const u32 old = atomicAdd(&g_count, 1u);
        if (old == (u32)NCTA * 512u - 1u) {
            g_count = 0u;
            st_release(&g_gen, 0u);
        }
    }
}

// ---------------- kernel 4: logits ----------------
__global__ void __launch_bounds__(256, 2)
k_logits(const float* __restrict__ dw, const float* __restrict__ db,
         float* __restrict__ out)
{
    __shared__ float smem[8192];
    const int tid = threadIdx.x;
    const int t   = blockIdx.x;
    const int vg  = tid >> 3;
    const int bg  = tid & 7;

    const float* hsrc = g_hs + (size_t)(t + 1) * HS;
    const u32 smem_u = smem_u32(smem);

    const float* W0 = dw + (vg * 4 + 0) * HIDDEN;
    const float* W1 = dw + (vg * 4 + 1) * HIDDEN;
    const float* W2 = dw + (vg * 4 + 2) * HIDDEN;
    const float* W3 = dw + (vg * 4 + 3) * HIDDEN;

    u64 acc[4][4];
#pragma unroll
    for (int vi = 0; vi < 4; vi++)
#pragma unroll
        for (int p = 0; p < 4; p++) acc[vi][p] = 0ull;

    {
#pragma unroll
        for (int i = 0; i < 4; i++) {
            const int slot = tid + i * 256;
            cpasync16(smem_u + slot * 16, hsrc + slot * 4);
        }
        cpcommit();
    }

    for (int kt = 0; kt < 16; ++kt) {
        const int buf = kt & 1;
        if (kt < 15) {
            const float* src = hsrc + (kt + 1) * 64 * 64;
            const u32 dst = smem_u + (buf ^ 1) * 4096 * 4;
#pragma unroll
            for (int i = 0; i < 4; i++) {
                const int slot = tid + i * 256;
                cpasync16(dst + slot * 16, src + slot * 4);
            }
            cpcommit();
            asm volatile("cp.async.wait_group 1;");
        } else {
            asm volatile("cp.async.wait_group 0;");
        }
        __syncthreads();

        const float* hb = smem + buf * 4096;
        const int kg0 = kt * 64;
#pragma unroll 4
        for (int c = 0; c < 16; c++) {
            const int kg = kg0 + c * 4;
            const float4 w0 = *(const float4*)(W0 + kg);
            const float4 w1 = *(const float4*)(W1 + kg);
            const float4 w2 = *(const float4*)(W2 + kg);
            const float4 w3 = *(const float4*)(W3 + kg);
#pragma unroll
            for (int i = 0; i < 4; i++) {
                const int kk = c * 4 + i;
                const u64* hp = (const u64*)(hb + kk * 64 + bg * 8);
                const u64 h0 = hp[0], h1 = hp[1], h2 = hp[2], h3 = hp[3];
                const u64 p0 = pack2((&w0.x)[i]);
                const u64 p1 = pack2((&w1.x)[i]);
                const u64 p2 = pack2((&w2.x)[i]);
                const u64 p3 = pack2((&w3.x)[i]);
                ffma2(acc[0][0], p0, h0); ffma2(acc[0][1], p0, h1);
                ffma2(acc[0][2], p0, h2); ffma2(acc[0][3], p0, h3);
                ffma2(acc[1][0], p1, h0); ffma2(acc[1][1], p1, h1);
                ffma2(acc[1][2], p1, h2); ffma2(acc[1][3], p1, h3);
                ffma2(acc[2][0], p2, h0); ffma2(acc[2][1], p2, h1);
                ffma2(acc[2][2], p2, h2); ffma2(acc[2][3], p2, h3);
                ffma2(acc[3][0], p3, h0); ffma2(acc[3][1], p3, h1);
                ffma2(acc[3][2], p3, h2); ffma2(acc[3][3], p3, h3);
            }
        }
        __syncthreads();
    }

    const float4 dbv = *(const float4*)(db + vg * 4);
#pragma unroll
    for (int p = 0; p < 4; p++) {
        float l0, h0, l1, h1, l2, h2, l3, h3;
        unpack2(acc[0][p], l0, h0); unpack2(acc[1][p], l1, h1);
        unpack2(acc[2][p], l2, h2); unpack2(acc[3][p], l3, h3);
        const int b0 = bg * 8 + 2 * p;
        float4 r0 = make_float4(l0 + dbv.x, l1 + dbv.y, l2 + dbv.z, l3 + dbv.w);
        float4 r1 = make_float4(h0 + dbv.x, h1 + dbv.y, h2 + dbv.z, h3 + dbv.w);
        *(float4*)(out + (size_t)(t * 64 + b0    ) * VOCAB + vg * 4) = r0;
        *(float4*)(out + (size_t)(t * 64 + b0 + 1) * VOCAB + vg * 4) = r1;
    }
}

// ---------------- kernel 5: h_final ----------------
__global__ void k_final(float* __restrict__ out2)
{
    const int o0 = (blockIdx.x * 256 + threadIdx.x) * 4;
    const float* src = g_hs + (size_t)SEQ * HS;
#pragma unroll
    for (int i = 0; i < 4; i++) {
        const int o = o0 + i;
        const int b = o >> 10, k = o & 1023;
        out2[b * HIDDEN + k] = src[k * 64 + b];
    }
}

// ---------------- launcher ----------------
extern "C" void kernel_launch(void* const* d_in, const int* in_sizes, int n_in,
                              void* d_out, int out_size)
{
    const int*   x    = (const int*)  d_in[0];
    const float* hprev= (const float*)d_in[1];
    const float* emb  = (const float*)d_in[2];
    const float* rxw  = (const float*)d_in[3];
    const float* rxb  = (const float*)d_in[4];
    const float* rhw  = (const float*)d_in[5];
    const float* rhb  = (const float*)d_in[6];
    const float* zxw  = (const float*)d_in[7];
    const float* zxb  = (const float*)d_in[8];
    const float* zhw  = (const float*)d_in[9];
    const float* zhb  = (const float*)d_in[10];
    const float* nxw  = (const float*)d_in[11];
    const float* nxb  = (const float*)d_in[12];
    const float* nhw  = (const float*)d_in[13];
    const float* nhb  = (const float*)d_in[14];
    const float* dw   = (const float*)d_in[15];
    const float* db   = (const float*)d_in[16];
    float* out = (float*)d_out;

    static bool attr_set = false;
    if (!attr_set) {
        cudaFuncSetAttribute(k_recur, cudaFuncAttributeMaxDynamicSharedMemorySize, SMEMB);
        attr_set = true;
    }

    k_tables<<<dim3(32, 3), 256>>>(emb, rxw, zxw, nxw, rxb, zxb, nxb);
    k_tr<<<64, 256>>>(hprev);
    k_recur<<<NCTA, 256, SMEMB>>>(x, rhw, rhb, zhw, zhb, nhw, nhb);
    k_logits<<<256, 256>>>(dw, db, out);
    k_final<<<64, 256>>>(out + (size_t)SEQ * BATCH * VOCAB);
}